// round 10
// baseline (speedup 1.0000x reference)
#include <cuda_runtime.h>
#include <cuda_bf16.h>
#include <math.h>
#include <stdint.h>

// Problem dims
#define B_   1024
#define H1   500
#define IN_  784
#define NOUT 10
#define T_   100
#define NP   512

// pass-0 (integer class-0) / pass-1 (5-slot corrections) padded K
#define K0P1 832     // 784 -> 13*64
#define K1P1 3968    // 784*5=3920 -> 62*64
#define K0P2 512     // 500 -> 8*64
#define K1P2 2560    // 500*5=2500 -> 40*64

// ---------------- device scratch ----------------
__device__ __align__(16) __nv_bfloat16 g_p0a1[(size_t)B_ * K0P1];
__device__ __align__(16) __nv_bfloat16 g_p0w1[(size_t)NP * K0P1];
__device__ __align__(16) __nv_bfloat16 g_p1a1[(size_t)B_ * K1P1];
__device__ __align__(16) __nv_bfloat16 g_p1w1[(size_t)NP * K1P1];
__device__ __align__(16) __nv_bfloat16 g_p0a2[(size_t)B_ * K0P2];
__device__ __align__(16) __nv_bfloat16 g_p0w2[(size_t)NP * K0P2];
__device__ __align__(16) __nv_bfloat16 g_p1a2[(size_t)B_ * K1P2];
__device__ __align__(16) __nv_bfloat16 g_p1w2[(size_t)NP * K1P2];
__device__ float g_sa1[B_], g_sw1[NP], g_sa2[B_], g_sw2[NP];
__device__ float g_h[B_ * H1];
__device__ float g_drive[B_ * H1];
__device__ float g_cf[T_];

// ---------------- helpers ----------------
#define SW128(o) ((o) ^ (((o) >> 3) & 0x70))

__device__ __forceinline__ uint32_t smem_u32(const void* p) {
    uint32_t a;
    asm("{ .reg .u64 t; cvta.to.shared.u64 t, %1; cvt.u32.u64 %0, t; }"
        : "=r"(a) : "l"(p));
    return a;
}
__device__ __forceinline__ void ldm_x4(uint32_t& r0, uint32_t& r1,
                                       uint32_t& r2, uint32_t& r3, uint32_t addr) {
    asm volatile("ldmatrix.sync.aligned.m8n8.x4.shared.b16 {%0,%1,%2,%3}, [%4];"
                 : "=r"(r0), "=r"(r1), "=r"(r2), "=r"(r3) : "r"(addr));
}
__device__ __forceinline__ void ldm_x2(uint32_t& r0, uint32_t& r1, uint32_t addr) {
    asm volatile("ldmatrix.sync.aligned.m8n8.x2.shared.b16 {%0,%1}, [%2];"
                 : "=r"(r0), "=r"(r1) : "r"(addr));
}
__device__ __forceinline__ void mma16816(float* c, const uint32_t* a, const uint32_t* b) {
    asm volatile("mma.sync.aligned.m16n8k16.row.col.f32.bf16.bf16.f32 "
                 "{%0,%1,%2,%3}, {%4,%5,%6,%7}, {%8,%9}, {%0,%1,%2,%3};"
                 : "+f"(c[0]), "+f"(c[1]), "+f"(c[2]), "+f"(c[3])
                 : "r"(a[0]), "r"(a[1]), "r"(a[2]), "r"(a[3]),
                   "r"(b[0]), "r"(b[1]));
}

// ---------------- integer limb extraction ----------------
// q = a*2^(8-e), |q| < 2^8 (e: rowmax < 2^e). A0=RN(q), A1=RN((q-A0)*256),
// A2=RN(((q-A0)*256-A1)*256). All integers <=256, exact in bf16 (p=8).
// a = 2^(e-8)*(A0 + A1/256 + A2/65536) + eps, |eps| <= 2^(e-25).
__device__ __forceinline__ void limbs_of(float a, float qs,
                                         float& A0, float& A1, float& A2) {
    const float q = a * qs;
    A0 = rintf(q);
    const float r1 = q - A0;                 // exact
    const float t1 = r1 * 256.0f;           // exact
    A1 = rintf(t1);
    const float r2 = t1 - A1;               // exact
    A2 = rintf(r2 * 256.0f);
}

// Row converter. ISA=true -> A-side slot pattern, else B-side.
// pass1 slot products (Aslot[r]*Bslot[r]):
//   r0: A0n*B1n  r1: A1n*B0n  (class 1 — both kept)
//   r2: A1n*B1n  r3: A0n*B2n  r4: A2n*B0n  (class 2)
template<int KD, int K0P, int K1P, bool ISA>
__device__ __forceinline__ void conv_row(const float* __restrict__ row, int valid,
                                         __nv_bfloat16* __restrict__ p0,
                                         __nv_bfloat16* __restrict__ p1,
                                         float* __restrict__ sarr, int ridx) {
    __shared__ float red[256];
    const int tid = threadIdx.x;
    float mx = 0.0f;
    if (valid)
        for (int k = tid; k < KD; k += 256) mx = fmaxf(mx, fabsf(row[k]));
    red[tid] = mx;
    __syncthreads();
    for (int s = 128; s; s >>= 1) {
        if (tid < s) red[tid] = fmaxf(red[tid], red[tid + s]);
        __syncthreads();
    }
    const float rm = red[0];
    int e = 0;
    if (rm > 0.0f) frexpf(rm, &e);           // rm = f*2^e, f in [0.5,1) -> rm < 2^e
    if (tid == 0) sarr[ridx] = ldexpf(1.0f, e - 8);
    const float qs = ldexpf(1.0f, 8 - e);
    const float s0 = ldexpf(1.0f, e - 8);
    const float s1 = ldexpf(1.0f, e - 16);
    const float s2 = ldexpf(1.0f, e - 24);

    for (int k = tid; k < KD; k += 256) {
        const float a = valid ? row[k] : 0.0f;
        float A0, A1, A2;
        limbs_of(a, qs, A0, A1, A2);
        p0[k] = __float2bfloat16(A0);        // exact (integer <= 256)
        const __nv_bfloat16 L0 = __float2bfloat16(A0 * s0);  // exact pow2 scales
        const __nv_bfloat16 L1 = __float2bfloat16(A1 * s1);
        const __nv_bfloat16 L2 = __float2bfloat16(A2 * s2);
        __nv_bfloat16* q5 = p1 + 5 * k;
        if (ISA) { q5[0] = L0; q5[1] = L1; q5[2] = L1; q5[3] = L0; q5[4] = L2; }
        else     { q5[0] = L1; q5[1] = L0; q5[2] = L1; q5[3] = L2; q5[4] = L0; }
    }
    const __nv_bfloat16 z = __float2bfloat16(0.0f);
    for (int k = KD + tid; k < K0P; k += 256) p0[k] = z;
    for (int c = 5 * KD + tid; c < K1P; c += 256) p1[c] = z;
}

__global__ void k_cA1(const float* __restrict__ x) {
    const int m = blockIdx.x;
    conv_row<IN_, K0P1, K1P1, true>(x + (long)m * IN_, 1,
        g_p0a1 + (long)m * K0P1, g_p1a1 + (long)m * K1P1, g_sa1, m);
}
__global__ void k_cW1(const float* __restrict__ w1) {
    const int n = blockIdx.x;
    conv_row<IN_, K0P1, K1P1, false>(w1 + (long)n * IN_, n < H1,
        g_p0w1 + (long)n * K0P1, g_p1w1 + (long)n * K1P1, g_sw1, n);
}
__global__ void k_cW2(const float* __restrict__ w2) {
    if (blockIdx.x == NP) {                  // extra block: cf[] in fp64
        if (threadIdx.x < T_) {
            const double r = 0.77880078307140487;   // exp(-1/4)
            const double q = 0.36787944117144233;   // exp(-1)
            const double tp1 = (double)(threadIdx.x + 1);
            const double rp = exp(-0.25 * tp1);
            const double qp = exp(-tp1);
            const double c = (r * (1.0 - rp) / (1.0 - r)
                            - q * (1.0 - qp) / (1.0 - q)) / (r - q);
            g_cf[threadIdx.x] = (float)c;
        }
        return;
    }
    const int n = blockIdx.x;
    conv_row<H1, K0P2, K1P2, false>(w2 + (long)n * H1, n < H1,
        g_p0w2 + (long)n * K0P2, g_p1w2 + (long)n * K1P2, g_sw2, n);
}
__global__ void k_cA2() {
    const int m = blockIdx.x;
    conv_row<H1, K0P2, K1P2, true>(g_h + (long)m * H1, 1,
        g_p0a2 + (long)m * K0P2, g_p1a2 + (long)m * K1P2, g_sa2, m);
}

// ---------------- HMMA pass (one operand pair, chunk-exact + RN drains) ----
__device__ __forceinline__ void gemm_pass(const __nv_bfloat16* __restrict__ Ag,
                                          const __nv_bfloat16* __restrict__ Bg,
                                          int KPE, int NC, int m0, int n0,
                                          const int* rowi, const int* dsti,
                                          const int* c8s, int warp, int lane,
                                          char (*sm)[16384], uint32_t smb,
                                          float* accS /*32 floats: [mt][nt][4]*/) {
#pragma unroll
    for (int i = 0; i < 4; i++) {
        *(uint4*)(sm[0] + dsti[i]) =
            *(const uint4*)(Ag + (long)(m0 + rowi[i]) * KPE + c8s[i]);
        *(uint4*)(sm[0] + 8192 + dsti[i]) =
            *(const uint4*)(Bg + (long)(n0 + rowi[i]) * KPE + c8s[i]);
    }
    __syncthreads();

    uint4 ra[4], rb[4];
    for (int c = 0; c < NC; c++) {
        const int cur = c & 1;
        if (c + 1 < NC) {
            const long ko = (long)(c + 1) * 64;
#pragma unroll
            for (int i = 0; i < 4; i++) {
                ra[i] = *(const uint4*)(Ag + (long)(m0 + rowi[i]) * KPE + ko + c8s[i]);
                rb[i] = *(const uint4*)(Bg + (long)(n0 + rowi[i]) * KPE + ko + c8s[i]);
            }
        }
        const uint32_t sA = smb + cur * 16384;
        const uint32_t sB = sA + 8192;

        float acc[2][4][4];
#pragma unroll
        for (int a = 0; a < 2; a++)
#pragma unroll
            for (int b = 0; b < 4; b++)
#pragma unroll
                for (int e2 = 0; e2 < 4; e2++) acc[a][b][e2] = 0.0f;

#pragma unroll
        for (int k16 = 0; k16 < 4; k16++) {
            uint32_t af[2][4], bf[4][2];
            const int rowa = (warp >> 1) * 32 + (lane & 15);
            const uint32_t kcol = k16 * 32 + (lane >> 4) * 16;
            ldm_x4(af[0][0], af[0][1], af[0][2], af[0][3],
                   sA + SW128((uint32_t)(rowa * 128) + kcol));
            ldm_x4(af[1][0], af[1][1], af[1][2], af[1][3],
                   sA + SW128((uint32_t)((rowa + 16) * 128) + kcol));
            const uint32_t kcolb = k16 * 32 + ((lane >> 3) & 1) * 16;
#pragma unroll
            for (int nt = 0; nt < 4; nt++) {
                const int rowb = (warp & 1) * 32 + nt * 8 + (lane & 7);
                ldm_x2(bf[nt][0], bf[nt][1],
                       sB + SW128((uint32_t)(rowb * 128) + kcolb));
            }
#pragma unroll
            for (int mt = 0; mt < 2; mt++)
#pragma unroll
                for (int nt = 0; nt < 4; nt++)
                    mma16816(acc[mt][nt], af[mt], bf[nt]);
        }
#pragma unroll
        for (int a = 0; a < 2; a++)
#pragma unroll
            for (int b = 0; b < 4; b++)
#pragma unroll
                for (int e2 = 0; e2 < 4; e2++)
                    accS[(a * 4 + b) * 4 + e2] =
                        __fadd_rn(accS[(a * 4 + b) * 4 + e2], acc[a][b][e2]);

        if (c + 1 < NC) {
            const int nx = cur ^ 1;
#pragma unroll
            for (int i = 0; i < 4; i++) {
                *(uint4*)(sm[nx] + dsti[i]) = ra[i];
                *(uint4*)(sm[nx] + 8192 + dsti[i]) = rb[i];
            }
            __syncthreads();
        }
    }
    __syncthreads();   // smem safe for next pass
}

// MODE 1: layer1 (relu -> g_h), MODE 2: layer2 (sigmoid -> g_drive)
template<int MODE>
__global__ void __launch_bounds__(128) k_mma(const float* __restrict__ bias) {
    __shared__ __align__(128) char sm[2][16384];
    const int tid = threadIdx.x, warp = tid >> 5, lane = tid & 31;
    const int m0 = blockIdx.y * 64, n0 = blockIdx.x * 64;

    int rowi[4], dsti[4], c8s[4];
#pragma unroll
    for (int i = 0; i < 4; i++) {
        const int e = tid + 128 * i;
        rowi[i] = e >> 3;
        dsti[i] = (int)SW128((uint32_t)((e >> 3) * 128 + (e & 7) * 16));
        c8s[i] = (e & 7) * 8;
    }

    const __nv_bfloat16 *A0g, *B0g, *A1g, *B1g;
    const float *sa, *sw;
    int K0, K1, NC0, NC1;
    if (MODE == 1) {
        A0g = g_p0a1; B0g = g_p0w1; A1g = g_p1a1; B1g = g_p1w1;
        sa = g_sa1; sw = g_sw1; K0 = K0P1; K1 = K1P1; NC0 = 13; NC1 = 62;
    } else {
        A0g = g_p0a2; B0g = g_p0w2; A1g = g_p1a2; B1g = g_p1w2;
        sa = g_sa2; sw = g_sw2; K0 = K0P2; K1 = K1P2; NC0 = 8; NC1 = 40;
    }

    float S0[32], S1[32];
#pragma unroll
    for (int i = 0; i < 32; i++) { S0[i] = 0.0f; S1[i] = 0.0f; }

    const uint32_t smb = smem_u32(sm);
    gemm_pass(A0g, B0g, K0, NC0, m0, n0, rowi, dsti, c8s, warp, lane, sm, smb, S0);
    gemm_pass(A1g, B1g, K1, NC1, m0, n0, rowi, dsti, c8s, warp, lane, sm, smb, S1);

    // epilogue: v = S0 * 2^(ea+eb-16) + S1 + bias (pow2 scale mul exact)
#pragma unroll
    for (int mt = 0; mt < 2; mt++) {
        const int gm0 = m0 + (warp >> 1) * 32 + mt * 16 + (lane >> 2);
#pragma unroll
        for (int nt = 0; nt < 4; nt++) {
            const int gn = n0 + (warp & 1) * 32 + nt * 8 + (lane & 3) * 2;
#pragma unroll
            for (int rr = 0; rr < 2; rr++) {
                const int m = gm0 + rr * 8;
                const float sam = sa[m];
#pragma unroll
                for (int jj = 0; jj < 2; jj++) {
                    const int n = gn + jj;
                    if (n >= H1) continue;
                    const float sab = sam * sw[n];
                    const int idx = (mt * 4 + nt) * 4 + rr * 2 + jj;
                    float v = __fadd_rn(__fmul_rn(S0[idx], sab), S1[idx]);
                    v = v + bias[n];
                    if (MODE == 1) {
                        g_h[(long)m * H1 + n] = fmaxf(v, 0.0f);
                    } else {
                        if (v >= 0.0f) v = 1.0f / (1.0f + expf(-v));
                        else { const float e = expf(v); v = e / (1.0f + e); }
                        g_drive[(long)m * H1 + n] = v;
                    }
                }
            }
        }
    }
}

// ---------------- fused gemm3 + LIF scan (proven exact) ----------------
__global__ void __launch_bounds__(256, 8)
k_fused3(const float* __restrict__ w3,
         const float* __restrict__ b3,
         float* __restrict__ out) {
    const int m = blockIdx.x;
    __shared__ float row[H1];
    __shared__ float part[250];
    __shared__ float cf[T_];
    __shared__ unsigned sbits[NOUT][4];

    const int tid = threadIdx.x;  // 256
    for (int k = tid; k < H1; k += 256) row[k] = g_drive[m * H1 + k];
    if (tid < T_) cf[tid] = g_cf[tid];
    __syncthreads();

    if (tid < 250) {
        const int n = tid / 25;
        const int ks = (tid % 25) * 20;
        float s = 0.0f;
#pragma unroll
        for (int k = 0; k < 20; k++)
            s = fmaf(row[ks + k], w3[n * H1 + ks + k], s);
        part[tid] = s;
    }
    __syncthreads();

    if (tid < NOUT) {
        float u = 0.0f;
#pragma unroll
        for (int p = 0; p < 25; p++) u += part[tid * 25 + p];

        const float bb = b3[tid];
        const int SIGB = __float_as_int(0.77880078307140487f);
        float v = 0.0f;
        float f = __int_as_float(SIGB);
        unsigned sb0 = 0, sb1 = 0, sb2 = 0, sb3v = 0;
#pragma unroll
        for (int t = 0; t < T_; t++) {
            const float cur = __fadd_rn(__fmul_rn(cf[t], u), bb);
            v = __fadd_rn(__fmul_rn(f, v), cur);
            const int tb = __float_as_int(__fadd_rn(v, -1.0f));
            const int smask = tb >> 31;
            f = __int_as_float(SIGB & smask);
            const unsigned bit = (unsigned)(~smask) & 1u;
            if (t < 32)       sb0 |= bit << t;
            else if (t < 64)  sb1 |= bit << (t - 32);
            else if (t < 96)  sb2 |= bit << (t - 64);
            else              sb3v |= bit << (t - 96);
        }
        sbits[tid][0] = sb0; sbits[tid][1] = sb1;
        sbits[tid][2] = sb2; sbits[tid][3] = sb3v;
    }
    __syncthreads();

    float* oblk = out + (size_t)m * NOUT * T_;
#pragma unroll
    for (int i = tid; i < NOUT * T_; i += 256) {
        const int n = i / T_;
        const int t = i - n * T_;
        const unsigned w = sbits[n][t >> 5];
        oblk[i] = (float)((w >> (t & 31)) & 1u);
    }
}

// ---------------- launch ----------------
extern "C" void kernel_launch(void* const* d_in, const int* in_sizes, int n_in,
                              void* d_out, int out_size) {
    const float* x  = (const float*)d_in[0];
    const float* w1 = (const float*)d_in[1];
    const float* b1 = (const float*)d_in[2];
    const float* w2 = (const float*)d_in[3];
    const float* b2 = (const float*)d_in[4];
    const float* w3 = (const float*)d_in[5];
    const float* b3 = (const float*)d_in[6];
    float* out = (float*)d_out;

    k_cA1<<<B_, 256>>>(x);
    k_cW1<<<NP, 256>>>(w1);
    k_cW2<<<NP + 1, 256>>>(w2);

    dim3 grid(NP / 64, B_ / 64);             // (8, 16) = 128 CTAs
    k_mma<1><<<grid, 128>>>(b1);
    k_cA2<<<B_, 256>>>();
    k_mma<2><<<grid, 128>>>(b2);

    k_fused3<<<B_, 256>>>(w3, b3, out);
}

// round 11
// speedup vs baseline: 1.2382x; 1.2382x over previous
#include <cuda_runtime.h>
#include <cuda_bf16.h>
#include <math.h>
#include <stdint.h>

// Problem dims
#define B_   1024
#define H1   500
#define IN_  784
#define NOUT 10
#define T_   100
#define NP   512

// pass-0 (integer class-0) / pass-1 (5-slot corrections) padded K
#define K0P1 832     // 784 -> 13*64
#define K1P1 3968    // 784*5=3920 -> 62*64
#define K0P2 512     // 500 -> 8*64
#define K1P2 2560    // 500*5=2500 -> 40*64

// ---------------- device scratch ----------------
__device__ __align__(16) __nv_bfloat16 g_p0a1[(size_t)B_ * K0P1];
__device__ __align__(16) __nv_bfloat16 g_p0w1[(size_t)NP * K0P1];
__device__ __align__(16) __nv_bfloat16 g_p1a1[(size_t)B_ * K1P1];
__device__ __align__(16) __nv_bfloat16 g_p1w1[(size_t)NP * K1P1];
__device__ __align__(16) __nv_bfloat16 g_p0a2[(size_t)B_ * K0P2];
__device__ __align__(16) __nv_bfloat16 g_p0w2[(size_t)NP * K0P2];
__device__ __align__(16) __nv_bfloat16 g_p1a2[(size_t)B_ * K1P2];
__device__ __align__(16) __nv_bfloat16 g_p1w2[(size_t)NP * K1P2];
__device__ float g_sa1[B_], g_sw1[NP], g_sa2[B_], g_sw2[NP];
__device__ float g_h[B_ * H1];
__device__ float g_drive[B_ * H1];
__device__ float g_cf[T_];

// ---------------- helpers ----------------
#define SW128(o) ((o) ^ (((o) >> 3) & 0x70))

__device__ __forceinline__ uint32_t smem_u32(const void* p) {
    uint32_t a;
    asm("{ .reg .u64 t; cvta.to.shared.u64 t, %1; cvt.u32.u64 %0, t; }"
        : "=r"(a) : "l"(p));
    return a;
}
__device__ __forceinline__ void cp_async16(uint32_t dst, const void* src) {
    asm volatile("cp.async.cg.shared.global [%0], [%1], 16;"
                 :: "r"(dst), "l"(src));
}
#define CP_COMMIT()  asm volatile("cp.async.commit_group;" ::: "memory")
#define CP_WAIT(n)   asm volatile("cp.async.wait_group %0;" :: "n"(n) : "memory")

__device__ __forceinline__ void ldm_x4(uint32_t& r0, uint32_t& r1,
                                       uint32_t& r2, uint32_t& r3, uint32_t addr) {
    asm volatile("ldmatrix.sync.aligned.m8n8.x4.shared.b16 {%0,%1,%2,%3}, [%4];"
                 : "=r"(r0), "=r"(r1), "=r"(r2), "=r"(r3) : "r"(addr));
}
__device__ __forceinline__ void ldm_x2(uint32_t& r0, uint32_t& r1, uint32_t addr) {
    asm volatile("ldmatrix.sync.aligned.m8n8.x2.shared.b16 {%0,%1}, [%2];"
                 : "=r"(r0), "=r"(r1) : "r"(addr));
}
__device__ __forceinline__ void mma16816(float* c, const uint32_t* a, const uint32_t* b) {
    asm volatile("mma.sync.aligned.m16n8k16.row.col.f32.bf16.bf16.f32 "
                 "{%0,%1,%2,%3}, {%4,%5,%6,%7}, {%8,%9}, {%0,%1,%2,%3};"
                 : "+f"(c[0]), "+f"(c[1]), "+f"(c[2]), "+f"(c[3])
                 : "r"(a[0]), "r"(a[1]), "r"(a[2]), "r"(a[3]),
                   "r"(b[0]), "r"(b[1]));
}

// ---------------- integer limb extraction (unchanged, proven exact) --------
__device__ __forceinline__ void limbs_of(float a, float qs,
                                         float& A0, float& A1, float& A2) {
    const float q = a * qs;
    A0 = rintf(q);
    const float r1 = q - A0;
    const float t1 = r1 * 256.0f;
    A1 = rintf(t1);
    const float r2 = t1 - A1;
    A2 = rintf(r2 * 256.0f);
}

template<int KD, int K0P, int K1P, bool ISA>
__device__ __forceinline__ void conv_row(const float* __restrict__ row, int valid,
                                         __nv_bfloat16* __restrict__ p0,
                                         __nv_bfloat16* __restrict__ p1,
                                         float* __restrict__ sarr, int ridx) {
    __shared__ float red[256];
    const int tid = threadIdx.x;
    float mx = 0.0f;
    if (valid)
        for (int k = tid; k < KD; k += 256) mx = fmaxf(mx, fabsf(row[k]));
    red[tid] = mx;
    __syncthreads();
    for (int s = 128; s; s >>= 1) {
        if (tid < s) red[tid] = fmaxf(red[tid], red[tid + s]);
        __syncthreads();
    }
    const float rm = red[0];
    int e = 0;
    if (rm > 0.0f) frexpf(rm, &e);
    if (tid == 0) sarr[ridx] = ldexpf(1.0f, e - 8);
    const float qs = ldexpf(1.0f, 8 - e);
    const float s0 = ldexpf(1.0f, e - 8);
    const float s1 = ldexpf(1.0f, e - 16);
    const float s2 = ldexpf(1.0f, e - 24);

    for (int k = tid; k < KD; k += 256) {
        const float a = valid ? row[k] : 0.0f;
        float A0, A1, A2;
        limbs_of(a, qs, A0, A1, A2);
        p0[k] = __float2bfloat16(A0);
        const __nv_bfloat16 L0 = __float2bfloat16(A0 * s0);
        const __nv_bfloat16 L1 = __float2bfloat16(A1 * s1);
        const __nv_bfloat16 L2 = __float2bfloat16(A2 * s2);
        __nv_bfloat16* q5 = p1 + 5 * k;
        if (ISA) { q5[0] = L0; q5[1] = L1; q5[2] = L1; q5[3] = L0; q5[4] = L2; }
        else     { q5[0] = L1; q5[1] = L0; q5[2] = L1; q5[3] = L2; q5[4] = L0; }
    }
    const __nv_bfloat16 z = __float2bfloat16(0.0f);
    for (int k = KD + tid; k < K0P; k += 256) p0[k] = z;
    for (int c = 5 * KD + tid; c < K1P; c += 256) p1[c] = z;
}

__global__ void k_cA1(const float* __restrict__ x) {
    const int m = blockIdx.x;
    conv_row<IN_, K0P1, K1P1, true>(x + (long)m * IN_, 1,
        g_p0a1 + (long)m * K0P1, g_p1a1 + (long)m * K1P1, g_sa1, m);
}
__global__ void k_cW1(const float* __restrict__ w1) {
    const int n = blockIdx.x;
    conv_row<IN_, K0P1, K1P1, false>(w1 + (long)n * IN_, n < H1,
        g_p0w1 + (long)n * K0P1, g_p1w1 + (long)n * K1P1, g_sw1, n);
}
__global__ void k_cW2(const float* __restrict__ w2) {
    if (blockIdx.x == NP) {                  // extra block: cf[] in fp64
        if (threadIdx.x < T_) {
            const double r = 0.77880078307140487;   // exp(-1/4)
            const double q = 0.36787944117144233;   // exp(-1)
            const double tp1 = (double)(threadIdx.x + 1);
            const double rp = exp(-0.25 * tp1);
            const double qp = exp(-tp1);
            const double c = (r * (1.0 - rp) / (1.0 - r)
                            - q * (1.0 - qp) / (1.0 - q)) / (r - q);
            g_cf[threadIdx.x] = (float)c;
        }
        return;
    }
    const int n = blockIdx.x;
    conv_row<H1, K0P2, K1P2, false>(w2 + (long)n * H1, n < H1,
        g_p0w2 + (long)n * K0P2, g_p1w2 + (long)n * K1P2, g_sw2, n);
}
__global__ void k_cA2() {
    const int m = blockIdx.x;
    conv_row<H1, K0P2, K1P2, true>(g_h + (long)m * H1, 1,
        g_p0a2 + (long)m * K0P2, g_p1a2 + (long)m * K1P2, g_sa2, m);
}

// ---------------- HMMA pass: cp.async 3-stage pipeline, 8 warps ------------
// CTA tile 64x64, warp tile 16x32 (4 M-warps x 2 N-warps).
// Numerics identical to R10: per-64-chunk fresh mma accumulator, RN drains.
__device__ __forceinline__ void issue_chunk(const __nv_bfloat16* __restrict__ Ag,
                                            const __nv_bfloat16* __restrict__ Bg,
                                            int KPE, int m0, int n0, int c,
                                            uint32_t stage_base, int tid) {
#pragma unroll
    for (int i = 0; i < 2; i++) {
        const int e = tid + 256 * i;           // 0..511
        const int row = e >> 3, c8 = e & 7;
        const uint32_t dst = SW128((uint32_t)(row * 128 + c8 * 16));
        cp_async16(stage_base + dst,
                   Ag + (long)(m0 + row) * KPE + (long)c * 64 + c8 * 8);
        cp_async16(stage_base + 8192 + dst,
                   Bg + (long)(n0 + row) * KPE + (long)c * 64 + c8 * 8);
    }
}

__device__ __forceinline__ void gemm_pass(const __nv_bfloat16* __restrict__ Ag,
                                          const __nv_bfloat16* __restrict__ Bg,
                                          int KPE, int NC, int m0, int n0,
                                          int wm, int wn, int lane, int tid,
                                          uint32_t smb, float* accS /*16*/) {
    issue_chunk(Ag, Bg, KPE, m0, n0, 0, smb, tid);
    CP_COMMIT();
    issue_chunk(Ag, Bg, KPE, m0, n0, 1, smb + 16384, tid);
    CP_COMMIT();

    for (int c = 0; c < NC; c++) {
        CP_WAIT(1);
        __syncthreads();
        if (c + 2 < NC) {
            issue_chunk(Ag, Bg, KPE, m0, n0, c + 2,
                        smb + ((c + 2) % 3) * 16384, tid);
            CP_COMMIT();
        }
        const uint32_t sA = smb + (c % 3) * 16384;
        const uint32_t sB = sA + 8192;

        float acc[4][4];
#pragma unroll
        for (int b = 0; b < 4; b++)
#pragma unroll
            for (int e2 = 0; e2 < 4; e2++) acc[b][e2] = 0.0f;

#pragma unroll
        for (int k16 = 0; k16 < 4; k16++) {
            uint32_t af[4], bf[4][2];
            const int rowa = wm * 16 + (lane & 15);
            const uint32_t kcol = (uint32_t)(k16 * 32 + (lane >> 4) * 16);
            ldm_x4(af[0], af[1], af[2], af[3],
                   sA + SW128((uint32_t)(rowa * 128) + kcol));
            const uint32_t kcolb = (uint32_t)(k16 * 32 + ((lane >> 3) & 1) * 16);
#pragma unroll
            for (int nt = 0; nt < 4; nt++) {
                const int rowb = wn * 32 + nt * 8 + (lane & 7);
                ldm_x2(bf[nt][0], bf[nt][1],
                       sB + SW128((uint32_t)(rowb * 128) + kcolb));
            }
#pragma unroll
            for (int nt = 0; nt < 4; nt++)
                mma16816(acc[nt], af, bf[nt]);
        }
#pragma unroll
        for (int b = 0; b < 4; b++)
#pragma unroll
            for (int e2 = 0; e2 < 4; e2++)
                accS[b * 4 + e2] = __fadd_rn(accS[b * 4 + e2], acc[b][e2]);
    }
    CP_WAIT(0);
    __syncthreads();
}

// MODE 1: layer1 (relu -> g_h), MODE 2: layer2 (sigmoid -> g_drive)
template<int MODE>
__global__ void __launch_bounds__(256) k_mma(const float* __restrict__ bias) {
    __shared__ __align__(128) char sm[3][16384];   // 48 KB, 3 stages
    const int tid = threadIdx.x;                   // 256
    const int warp = tid >> 5, lane = tid & 31;
    const int wm = warp & 3, wn = warp >> 2;       // 4 x 2 warp grid
    const int m0 = blockIdx.y * 64, n0 = blockIdx.x * 64;

    const __nv_bfloat16 *A0g, *B0g, *A1g, *B1g;
    const float *sa, *sw;
    int K0, K1, NC0, NC1;
    if (MODE == 1) {
        A0g = g_p0a1; B0g = g_p0w1; A1g = g_p1a1; B1g = g_p1w1;
        sa = g_sa1; sw = g_sw1; K0 = K0P1; K1 = K1P1; NC0 = 13; NC1 = 62;
    } else {
        A0g = g_p0a2; B0g = g_p0w2; A1g = g_p1a2; B1g = g_p1w2;
        sa = g_sa2; sw = g_sw2; K0 = K0P2; K1 = K1P2; NC0 = 8; NC1 = 40;
    }

    float S0[16], S1[16];
#pragma unroll
    for (int i = 0; i < 16; i++) { S0[i] = 0.0f; S1[i] = 0.0f; }

    const uint32_t smb = smem_u32(sm);
    gemm_pass(A0g, B0g, K0, NC0, m0, n0, wm, wn, lane, tid, smb, S0);
    gemm_pass(A1g, B1g, K1, NC1, m0, n0, wm, wn, lane, tid, smb, S1);

    // epilogue: v = RN(S0 * 2^(ea+eb-16)) + S1 + bias (pow2 scale mul exact)
#pragma unroll
    for (int nt = 0; nt < 4; nt++) {
        const int gn = n0 + wn * 32 + nt * 8 + (lane & 3) * 2;
#pragma unroll
        for (int rr = 0; rr < 2; rr++) {
            const int m = m0 + wm * 16 + (lane >> 2) + rr * 8;
            const float sam = sa[m];
#pragma unroll
            for (int jj = 0; jj < 2; jj++) {
                const int n = gn + jj;
                if (n >= H1) continue;
                const float sab = sam * sw[n];
                const int idx = nt * 4 + rr * 2 + jj;
                float v = __fadd_rn(__fmul_rn(S0[idx], sab), S1[idx]);
                v = v + bias[n];
                if (MODE == 1) {
                    g_h[(long)m * H1 + n] = fmaxf(v, 0.0f);
                } else {
                    if (v >= 0.0f) v = 1.0f / (1.0f + expf(-v));
                    else { const float e = expf(v); v = e / (1.0f + e); }
                    g_drive[(long)m * H1 + n] = v;
                }
            }
        }
    }
}

// ---------------- fused gemm3 + LIF scan (proven exact) ----------------
__global__ void __launch_bounds__(256, 8)
k_fused3(const float* __restrict__ w3,
         const float* __restrict__ b3,
         float* __restrict__ out) {
    const int m = blockIdx.x;
    __shared__ float row[H1];
    __shared__ float part[250];
    __shared__ float cf[T_];
    __shared__ unsigned sbits[NOUT][4];

    const int tid = threadIdx.x;  // 256
    for (int k = tid; k < H1; k += 256) row[k] = g_drive[m * H1 + k];
    if (tid < T_) cf[tid] = g_cf[tid];
    __syncthreads();

    if (tid < 250) {
        const int n = tid / 25;
        const int ks = (tid % 25) * 20;
        float s = 0.0f;
#pragma unroll
        for (int k = 0; k < 20; k++)
            s = fmaf(row[ks + k], w3[n * H1 + ks + k], s);
        part[tid] = s;
    }
    __syncthreads();

    if (tid < NOUT) {
        float u = 0.0f;
#pragma unroll
        for (int p = 0; p < 25; p++) u += part[tid * 25 + p];

        const float bb = b3[tid];
        const int SIGB = __float_as_int(0.77880078307140487f);
        float v = 0.0f;
        float f = __int_as_float(SIGB);
        unsigned sb0 = 0, sb1 = 0, sb2 = 0, sb3v = 0;
#pragma unroll
        for (int t = 0; t < T_; t++) {
            const float cur = __fadd_rn(__fmul_rn(cf[t], u), bb);
            v = __fadd_rn(__fmul_rn(f, v), cur);
            const int tb = __float_as_int(__fadd_rn(v, -1.0f));
            const int smask = tb >> 31;
            f = __int_as_float(SIGB & smask);
            const unsigned bit = (unsigned)(~smask) & 1u;
            if (t < 32)       sb0 |= bit << t;
            else if (t < 64)  sb1 |= bit << (t - 32);
            else if (t < 96)  sb2 |= bit << (t - 64);
            else              sb3v |= bit << (t - 96);
        }
        sbits[tid][0] = sb0; sbits[tid][1] = sb1;
        sbits[tid][2] = sb2; sbits[tid][3] = sb3v;
    }
    __syncthreads();

    float* oblk = out + (size_t)m * NOUT * T_;
#pragma unroll
    for (int i = tid; i < NOUT * T_; i += 256) {
        const int n = i / T_;
        const int t = i - n * T_;
        const unsigned w = sbits[n][t >> 5];
        oblk[i] = (float)((w >> (t & 31)) & 1u);
    }
}

// ---------------- launch ----------------
extern "C" void kernel_launch(void* const* d_in, const int* in_sizes, int n_in,
                              void* d_out, int out_size) {
    const float* x  = (const float*)d_in[0];
    const float* w1 = (const float*)d_in[1];
    const float* b1 = (const float*)d_in[2];
    const float* w2 = (const float*)d_in[3];
    const float* b2 = (const float*)d_in[4];
    const float* w3 = (const float*)d_in[5];
    const float* b3 = (const float*)d_in[6];
    float* out = (float*)d_out;

    k_cA1<<<B_, 256>>>(x);
    k_cW1<<<NP, 256>>>(w1);
    k_cW2<<<NP + 1, 256>>>(w2);

    dim3 grid(NP / 64, B_ / 64);             // (8, 16) = 128 CTAs
    k_mma<1><<<grid, 256>>>(b1);
    k_cA2<<<B_, 256>>>();
    k_mma<2><<<grid, 256>>>(b2);

    k_fused3<<<B_, 256>>>(w3, b3, out);
}